// round 8
// baseline (speedup 1.0000x reference)
#include <cuda_runtime.h>
#include <cstdint>

#define FULLMASK 0xffffffffu

constexpr int C      = 1024;   // columns per row
constexpr int KTOP   = 30;     // top-k
constexpr int WPB    = 8;      // warps (rows in flight) per block
constexpr int NBLK   = 1184;   // persistent grid: 148 SMs x 8 resident 256-thr blocks
constexpr int MAXBLK = 2048;

// Per-block partial results (written unconditionally -> no zeroing needed).
__device__ float  g_match_part[MAXBLK];
__device__ double g_diff_part[MAXBLK];

__device__ __forceinline__ unsigned f2o(float f) {
    unsigned u = __float_as_uint(f);
    return (u & 0x80000000u) ? ~u : (u | 0x80000000u);
}
__device__ __forceinline__ float o2f(unsigned k) {
    unsigned u = (k & 0x80000000u) ? (k & 0x7fffffffu) : ~k;
    return __uint_as_float(u);
}
__device__ __forceinline__ unsigned umx(unsigned a, unsigned b) { return a > b ? a : b; }
__device__ __forceinline__ unsigned umn(unsigned a, unsigned b) { return a < b ? a : b; }

struct WarpScratch {
    unsigned keys[64];   // candidate keys (orderable u32)
    int      idx[2][32]; // top-30 index lists for tensor 0/1 (capacity 32)
};

// One bitonic compare-exchange phase on 64 elements (2 per lane).
#define PH(K_, J_) {                                                             \
    unsigned x0 = __shfl_xor_sync(FULLMASK, k0, (J_));                           \
    unsigned x1 = __shfl_xor_sync(FULLMASK, k1, (J_));                           \
    bool m0 = (((lane)      & (K_)) == 0) == (((lane)      & (J_)) == 0);        \
    bool m1 = ((((lane)+32) & (K_)) == 0) == ((((lane)+32) & (J_)) == 0);        \
    k0 = m0 ? umx(k0, x0) : umn(k0, x0);                                         \
    k1 = m1 ? umx(k1, x1) : umn(k1, x1);                                         \
}

// Processes one row of one tensor. Fills ws.idx[which][0..29] with the top-30
// column indices (unordered set) and returns, for lane l < 30, the l-th largest
// value of the row (exact fp32). Other lanes return 0.
__device__ __forceinline__ float process_row(const float* __restrict__ src,
                                             int row, int lane,
                                             WarpScratch& ws, int which,
                                             unsigned lanemask_lt) {
    const float NEG_INF = __int_as_float(0xff800000);
    float v[32];
    const float4* p = reinterpret_cast<const float4*>(src + (size_t)row * C);
#pragma unroll
    for (int q = 0; q < 8; q++) {
        float4 t = p[q * 32 + lane];
        v[q * 4 + 0] = t.x; v[q * 4 + 1] = t.y;
        v[q * 4 + 2] = t.z; v[q * 4 + 3] = t.w;
    }

    // Gather candidates above fixed threshold via ballot-prefix compaction
    // (P(X>T0) ~ 45/1024 for N(0,1); count in [30,64] w.p. ~98.7%).
    const float T0 = 1.7059f;
    int base = 0;
#pragma unroll
    for (int j = 0; j < 32; j++) {
        bool pr = v[j] > T0;
        unsigned b = __ballot_sync(FULLMASK, pr);
        if (pr) {
            int pos = base + __popc(b & lanemask_lt);
            if (pos < 64) ws.keys[pos] = f2o(v[j]);
        }
        base += __popc(b);
    }
    int c = base;
    __syncwarp();

    unsigned k0 = 0, k1 = 0;

    if (c >= KTOP && c <= 64) {
        // --- fast path: bitonic sort 64 candidate keys, descending ---
        if (lane      >= c) ws.keys[lane]      = 0u;
        if (lane + 32 >= c) ws.keys[lane + 32] = 0u;
        __syncwarp();
        k0 = ws.keys[lane];
        k1 = ws.keys[lane + 32];

        PH(2, 1);
        PH(4, 2);  PH(4, 1);
        PH(8, 4);  PH(8, 2);  PH(8, 1);
        PH(16, 8); PH(16, 4); PH(16, 2); PH(16, 1);
        PH(32, 16); PH(32, 8); PH(32, 4); PH(32, 2); PH(32, 1);
        { unsigned a = umx(k0, k1), b = umn(k0, k1); k0 = a; k1 = b; } // k=64, j=32
        PH(64, 16); PH(64, 8); PH(64, 4); PH(64, 2); PH(64, 1);

        // lane l holds the l-th largest key (l < 32) in k0.
        float vmin = o2f(__shfl_sync(FULLMASK, k0, KTOP - 1));

        // Index recovery: every element >= 30th value is a top-30 member.
        int b2 = 0;
#pragma unroll
        for (int j = 0; j < 32; j++) {
            bool pr = v[j] >= vmin;
            unsigned b = __ballot_sync(FULLMASK, pr);
            if (pr) {
                int pos = b2 + __popc(b & lanemask_lt);
                if (pos < KTOP)
                    ws.idx[which][pos] = ((j >> 2) << 7) + (lane << 2) + (j & 3);
            }
            b2 += __popc(b);
        }
        __syncwarp();
    } else {
        // --- rare fallback (~1.3% of rows): exact 30-step warp extraction ---
        float bestv = NEG_INF; int bestj = 0;
#pragma unroll
        for (int j = 0; j < 32; j++)
            if (v[j] > bestv) { bestv = v[j]; bestj = j; }

#pragma unroll 1
        for (int i = 0; i < KTOP; i++) {
            unsigned key = f2o(bestv);
            unsigned wk = key;
#pragma unroll
            for (int s = 16; s; s >>= 1)
                wk = umx(wk, __shfl_xor_sync(FULLMASK, wk, s));
            int winner = __ffs(__ballot_sync(FULLMASK, key == wk)) - 1;
            int gj = ((bestj >> 2) << 7) + (lane << 2) + (bestj & 3);
            int gwin = __shfl_sync(FULLMASK, gj, winner);
            if (lane == i) k0 = wk;
            if (lane == 0) ws.idx[which][i] = gwin;
            if (lane == winner) {
                float nb = NEG_INF; int nj = 0;
#pragma unroll
                for (int j = 0; j < 32; j++) {
                    float vj = (j == bestj) ? NEG_INF : v[j];
                    if (j == bestj) v[j] = NEG_INF;
                    if (vj > nb) { nb = vj; nj = j; }
                }
                bestv = nb; bestj = nj;
            }
            __syncwarp();
        }
    }

    return (lane < KTOP) ? o2f(k0) : 0.0f;
}

__global__ void __launch_bounds__(WPB * 32)
topk_main_kernel(const float* __restrict__ A, const float* __restrict__ B, int nrows) {
    __shared__ WarpScratch ws[WPB];
    __shared__ int    s_match[WPB];
    __shared__ double s_diff[WPB];

    int w = threadIdx.x >> 5;
    int lane = threadIdx.x & 31;
    unsigned lanemask_lt = (lane == 0) ? 0u : (FULLMASK >> (32 - lane));

    int    match_acc = 0;
    double diff_acc  = 0.0;

    for (int row = blockIdx.x * WPB + w; row < nrows; row += NBLK * WPB) {
        float va = process_row(A, row, lane, ws[w], 0, lanemask_lt);
        float vb = process_row(B, row, lane, ws[w], 1, lanemask_lt);

        // diff: sum_k |v_pred[k] - v_topk[k]| for this row
        float d = (lane < KTOP) ? fabsf(va - vb) : 0.0f;
#pragma unroll
        for (int s = 16; s; s >>= 1)
            d += __shfl_xor_sync(FULLMASK, d, s);

        // match: |idx set A ∩ idx set B|
        int ia = (lane < KTOP) ? ws[w].idx[0][lane] : -1;
        bool m = false;
#pragma unroll
        for (int j = 0; j < KTOP; j++) {
            int ib = ws[w].idx[1][j];   // uniform address -> LDS broadcast
            m |= (ia == ib);
        }
        int mc = __popc(__ballot_sync(FULLMASK, m));

        match_acc += mc;
        diff_acc  += (double)d;
    }

    if (lane == 0) { s_match[w] = match_acc; s_diff[w] = diff_acc; }
    __syncthreads();
    if (threadIdx.x == 0) {
        int mt = 0; double dt = 0.0;
#pragma unroll
        for (int i = 0; i < WPB; i++) { mt += s_match[i]; dt += s_diff[i]; }
        g_match_part[blockIdx.x] = (float)mt;
        g_diff_part[blockIdx.x]  = dt;
    }
}

__global__ void topk_finalize_kernel(float* __restrict__ out, int nblocks, int nrows) {
    __shared__ double sm[256];
    __shared__ double sd[256];
    // Independent accumulators per thread; <=5 strided loads each -> full MLP.
    double m = 0.0, d = 0.0;
    for (int i = threadIdx.x; i < nblocks; i += 256) {
        m += (double)g_match_part[i];
        d += g_diff_part[i];
    }
    sm[threadIdx.x] = m;
    sd[threadIdx.x] = d;
    __syncthreads();
    for (int s = 128; s; s >>= 1) {
        if (threadIdx.x < s) {
            sm[threadIdx.x] += sm[threadIdx.x + s];
            sd[threadIdx.x] += sd[threadIdx.x + s];
        }
        __syncthreads();
    }
    if (threadIdx.x == 0) {
        out[0] = (float)(sm[0] / ((double)KTOP * (double)nrows)); // acc
        out[1] = (float)(sd[0] / (double)KTOP);                   // diff
    }
}

extern "C" void kernel_launch(void* const* d_in, const int* in_sizes, int n_in,
                              void* d_out, int out_size) {
    const float* A = (const float*)d_in[0];  // pred  (symmetric: order irrelevant)
    const float* B = (const float*)d_in[1];  // target
    int nrows = in_sizes[0] / C;

    topk_main_kernel<<<NBLK, WPB * 32>>>(A, B, nrows);
    topk_finalize_kernel<<<1, 256>>>((float*)d_out, NBLK, nrows);
}

// round 9
// speedup vs baseline: 1.8620x; 1.8620x over previous
#include <cuda_runtime.h>
#include <cstdint>

#define FULLMASK 0xffffffffu

constexpr int C    = 1024;   // columns per row
constexpr int KTOP = 30;     // top-k
constexpr int WPB  = 8;      // warps (rows in flight) per block
constexpr int NBLK = 1184;   // grid blocks (persistent-ish, grid-stride)

// Per-block partials (written unconditionally every launch -> no zeroing needed).
__device__ float  g_match_part[NBLK];
__device__ double g_diff_part[NBLK];
__device__ int    g_done = 0;   // reset to 0 by last block each launch

__device__ __forceinline__ unsigned f2o(float f) {
    unsigned u = __float_as_uint(f);
    return (u & 0x80000000u) ? ~u : (u | 0x80000000u);
}
__device__ __forceinline__ float o2f(unsigned k) {
    unsigned u = (k & 0x80000000u) ? (k & 0x7fffffffu) : ~k;
    return __uint_as_float(u);
}
__device__ __forceinline__ unsigned umx(unsigned a, unsigned b) { return a > b ? a : b; }
__device__ __forceinline__ unsigned umn(unsigned a, unsigned b) { return a < b ? a : b; }

// One bitonic compare-exchange phase on 64 elements (2 per lane). Descending.
#define PH(K_, J_) {                                                             \
    unsigned x0 = __shfl_xor_sync(FULLMASK, k0, (J_));                           \
    unsigned x1 = __shfl_xor_sync(FULLMASK, k1, (J_));                           \
    bool m0 = (((lane)      & (K_)) == 0) == (((lane)      & (J_)) == 0);        \
    bool m1 = ((((lane)+32) & (K_)) == 0) == ((((lane)+32) & (J_)) == 0);        \
    k0 = m0 ? umx(k0, x0) : umn(k0, x0);                                         \
    k1 = m1 ? umx(k1, x1) : umn(k1, x1);                                         \
}

// Processes one row of one tensor.
// Returns: for lane l < 30, the l-th largest value of the row (exact fp32).
// mask_out: bit j set iff this lane's element j is a top-30 member.
__device__ __forceinline__ float process_row(const float* __restrict__ src,
                                             int row, int lane,
                                             unsigned* __restrict__ keys, // shared[64]
                                             unsigned& mask_out) {
    const float NEG_INF = __int_as_float(0xff800000);
    float v[32];
    const float4* p = reinterpret_cast<const float4*>(src + (size_t)row * C);
#pragma unroll
    for (int q = 0; q < 8; q++) {
        float4 t = p[q * 32 + lane];
        v[q * 4 + 0] = t.x; v[q * 4 + 1] = t.y;
        v[q * 4 + 2] = t.z; v[q * 4 + 3] = t.w;
    }

    // Per-lane candidate count (independent compares; no warp ops).
    // P(X > T0) ~ 45/1024 for N(0,1); warp total in [30,64] w.p. ~98.7%.
    const float T0 = 1.7059f;
    int cnt = 0;
#pragma unroll
    for (int j = 0; j < 32; j++) cnt += (v[j] > T0) ? 1 : 0;

    // Single warp inclusive prefix-scan (5 shfl_up) -> per-lane write base.
    int pre = cnt;
#pragma unroll
    for (int s = 1; s < 32; s <<= 1) {
        int t = __shfl_up_sync(FULLMASK, pre, s);
        if (lane >= s) pre += t;
    }
    int total = __shfl_sync(FULLMASK, pre, 31);
    int base  = pre - cnt;   // exclusive prefix

    unsigned k0 = 0;
    unsigned mask = 0;

    if (total >= KTOP && total <= 64) {
        // --- fast path: each lane streams its candidates to shared ---
        int pos = base;
#pragma unroll
        for (int j = 0; j < 32; j++) {
            if (v[j] > T0) { keys[pos] = f2o(v[j]); pos++; }
        }
        __syncwarp();
        k0          = (lane      < total) ? keys[lane]      : 0u;
        unsigned k1 = (lane + 32 < total) ? keys[lane + 32] : 0u;

        // Bitonic sort 64 keys, descending.
        PH(2, 1);
        PH(4, 2);  PH(4, 1);
        PH(8, 4);  PH(8, 2);  PH(8, 1);
        PH(16, 8); PH(16, 4); PH(16, 2); PH(16, 1);
        PH(32, 16); PH(32, 8); PH(32, 4); PH(32, 2); PH(32, 1);
        { unsigned a = umx(k0, k1), b = umn(k0, k1); k0 = a; k1 = b; } // k=64,j=32
        PH(64, 16); PH(64, 8); PH(64, 4); PH(64, 2); PH(64, 1);

        // lane l holds the l-th largest key (l < 32) in k0.
        float vmin = o2f(__shfl_sync(FULLMASK, k0, KTOP - 1));

        // Membership mask: element j is top-30 iff >= 30th value.
#pragma unroll
        for (int j = 0; j < 32; j++)
            if (v[j] >= vmin) mask |= (1u << j);
        __syncwarp();
    } else {
        // --- rare fallback (~1.3% of rows): exact 30-step warp extraction ---
        float bestv = NEG_INF; int bestj = 0;
#pragma unroll
        for (int j = 0; j < 32; j++)
            if (v[j] > bestv) { bestv = v[j]; bestj = j; }

#pragma unroll 1
        for (int i = 0; i < KTOP; i++) {
            unsigned key = f2o(bestv);
            unsigned wk = key;
#pragma unroll
            for (int s = 16; s; s >>= 1)
                wk = umx(wk, __shfl_xor_sync(FULLMASK, wk, s));
            int winner = __ffs(__ballot_sync(FULLMASK, key == wk)) - 1;
            if (lane == i) k0 = wk;
            if (lane == winner) {
                mask |= (1u << bestj);           // exact membership, handles ties
                float nb = NEG_INF; int nj = 0;
#pragma unroll
                for (int j = 0; j < 32; j++) {
                    float vj = (j == bestj) ? NEG_INF : v[j];
                    if (j == bestj) v[j] = NEG_INF;
                    if (vj > nb) { nb = vj; nj = j; }
                }
                bestv = nb; bestj = nj;
            }
            __syncwarp();
        }
    }

    mask_out = mask;
    return (lane < KTOP) ? o2f(k0) : 0.0f;
}

__global__ void __launch_bounds__(WPB * 32)
topk_main_kernel(const float* __restrict__ A, const float* __restrict__ B,
                 int nrows, float* __restrict__ out) {
    __shared__ unsigned s_keys[WPB][64];
    __shared__ int      s_match[WPB];
    __shared__ double   s_diff[WPB];
    __shared__ int      s_last;

    int w = threadIdx.x >> 5;
    int lane = threadIdx.x & 31;

    int    match_acc = 0;
    double diff_acc  = 0.0;

    for (int row = blockIdx.x * WPB + w; row < nrows; row += NBLK * WPB) {
        unsigned ma, mb;
        float va = process_row(A, row, lane, s_keys[w], ma);
        float vb = process_row(B, row, lane, s_keys[w], mb);

        // diff: sum_k |v_pred[k] - v_topk[k]|  (paired sorted values)
        float d = (lane < KTOP) ? fabsf(va - vb) : 0.0f;
        // match: membership-mask intersection (no index lists needed)
        int m = __popc(ma & mb);
#pragma unroll
        for (int s = 16; s; s >>= 1) {
            d += __shfl_xor_sync(FULLMASK, d, s);
            m += __shfl_xor_sync(FULLMASK, m, s);
        }
        match_acc += m;
        diff_acc  += (double)d;
    }

    if (lane == 0) { s_match[w] = match_acc; s_diff[w] = diff_acc; }
    __syncthreads();

    if (threadIdx.x == 0) {
        int mt = 0; double dt = 0.0;
#pragma unroll
        for (int i = 0; i < WPB; i++) { mt += s_match[i]; dt += s_diff[i]; }
        g_match_part[blockIdx.x] = (float)mt;
        g_diff_part[blockIdx.x]  = dt;
        __threadfence();
        int ticket = atomicAdd(&g_done, 1);
        s_last = (ticket == NBLK - 1) ? 1 : 0;
    }
    __syncthreads();

    // Last finishing block reduces the (L2-hot) partials and writes the output.
    if (s_last) {
        __shared__ double sm[256];
        __shared__ double sd[256];
        double m = 0.0, d = 0.0;
        for (int i = threadIdx.x; i < NBLK; i += WPB * 32) {
            m += (double)g_match_part[i];
            d += g_diff_part[i];
        }
        sm[threadIdx.x] = m;
        sd[threadIdx.x] = d;
        __syncthreads();
        for (int s = (WPB * 32) / 2; s; s >>= 1) {
            if (threadIdx.x < s) {
                sm[threadIdx.x] += sm[threadIdx.x + s];
                sd[threadIdx.x] += sd[threadIdx.x + s];
            }
            __syncthreads();
        }
        if (threadIdx.x == 0) {
            out[0] = (float)(sm[0] / ((double)KTOP * (double)nrows)); // acc
            out[1] = (float)(sd[0] / (double)KTOP);                   // diff
            g_done = 0;   // restore for next graph replay (deterministic)
        }
    }
}

extern "C" void kernel_launch(void* const* d_in, const int* in_sizes, int n_in,
                              void* d_out, int out_size) {
    const float* A = (const float*)d_in[0];  // pred  (metric is symmetric in inputs)
    const float* B = (const float*)d_in[1];  // target
    int nrows = in_sizes[0] / C;

    topk_main_kernel<<<NBLK, WPB * 32>>>(A, B, nrows, (float*)d_out);
}

// round 10
// speedup vs baseline: 1.9509x; 1.0478x over previous
#include <cuda_runtime.h>
#include <cstdint>

#define FULLMASK 0xffffffffu

constexpr int C    = 1024;   // columns per row
constexpr int KTOP = 30;     // top-k
constexpr int WPB  = 8;      // warps (rows in flight) per block
constexpr int NBLK = 1184;   // grid blocks (grid-stride over rows)

// Per-block partials (written unconditionally every launch -> no zeroing needed).
__device__ float  g_match_part[NBLK];
__device__ double g_diff_part[NBLK];
__device__ int    g_done = 0;   // reset to 0 by last block each launch

// Dual bitonic phase: k0 sorted descending, k1 ascending (inverted direction).
#define DUAL(K_, J_) {                                                          \
    float x0 = __shfl_xor_sync(FULLMASK, k0, (J_));                             \
    float x1 = __shfl_xor_sync(FULLMASK, k1, (J_));                             \
    bool up = (((lane) & (K_)) == 0) == (((lane) & (J_)) == 0);                 \
    k0 = up ? fmaxf(k0, x0) : fminf(k0, x0);                                    \
    k1 = up ? fminf(k1, x1) : fmaxf(k1, x1);                                    \
}
// Bitonic merge phase on k0 only (descending).
#define MERGE(J_) {                                                             \
    float x0 = __shfl_xor_sync(FULLMASK, k0, (J_));                             \
    k0 = (((lane) & (J_)) == 0) ? fmaxf(k0, x0) : fminf(k0, x0);                \
}

// Processes one row of one tensor.
// Returns: for lane l < 30, the l-th largest value of the row (exact fp32).
// mask_out: bit j set iff this lane's element j is a top-30 member.
__device__ __forceinline__ float process_row(const float* __restrict__ src,
                                             int row, int lane,
                                             float* __restrict__ keys, // shared[64]
                                             unsigned& mask_out) {
    const float NEG_INF = __int_as_float(0xff800000);
    float v[32];
    const float4* p = reinterpret_cast<const float4*>(src + (size_t)row * C);
#pragma unroll
    for (int q = 0; q < 8; q++) {
        float4 t = p[q * 32 + lane];
        v[q * 4 + 0] = t.x; v[q * 4 + 1] = t.y;
        v[q * 4 + 2] = t.z; v[q * 4 + 3] = t.w;
    }

    // Per-lane candidate count (independent compares; no warp ops).
    // P(X > T0) ~ 45/1024 for N(0,1); warp total in [30,64] w.p. ~98.7%.
    const float T0 = 1.7059f;
    int cnt = 0;
#pragma unroll
    for (int j = 0; j < 32; j++) cnt += (v[j] > T0) ? 1 : 0;

    // Warp inclusive prefix-scan (5 shfl_up) -> per-lane write base.
    int pre = cnt;
#pragma unroll
    for (int s = 1; s < 32; s <<= 1) {
        int t = __shfl_up_sync(FULLMASK, pre, s);
        if (lane >= s) pre += t;
    }
    int total = __shfl_sync(FULLMASK, pre, 31);
    int base  = pre - cnt;   // exclusive prefix

    float k0 = 0.0f;
    unsigned mask = 0;

    if (total >= KTOP && total <= 64) {
        // --- fast path: stream candidates (positive floats, no key transform) ---
        int pos = base;
#pragma unroll
        for (int j = 0; j < 32; j++) {
            if (v[j] > T0) { keys[pos] = v[j]; pos++; }
        }
        __syncwarp();
        k0       = (lane      < total) ? keys[lane]      : 0.0f;
        float k1 = (lane + 32 < total) ? keys[lane + 32] : 0.0f;
        __syncwarp();   // reads done before any future overwrite of keys

        // Dual 32-sort: k0 descending, k1 ascending (15 phases).
        DUAL(2, 1);
        DUAL(4, 2);  DUAL(4, 1);
        DUAL(8, 4);  DUAL(8, 2);  DUAL(8, 1);
        DUAL(16, 8); DUAL(16, 4); DUAL(16, 2); DUAL(16, 1);
        DUAL(32, 16); DUAL(32, 8); DUAL(32, 4); DUAL(32, 2); DUAL(32, 1);
        // Elementwise max of (desc, asc) = top-32 multiset, bitonic order.
        k0 = fmaxf(k0, k1);
        // 5-phase bitonic merge -> k0 descending = top-32 sorted.
        MERGE(16); MERGE(8); MERGE(4); MERGE(2); MERGE(1);

        float vmin = __shfl_sync(FULLMASK, k0, KTOP - 1);

        // Membership mask: element j is a top-30 member iff >= 30th value.
#pragma unroll
        for (int j = 0; j < 32; j++)
            if (v[j] >= vmin) mask |= (1u << j);
    } else {
        // --- rare fallback (~1.3% of rows): exact 30-step warp extraction ---
        float bestv = NEG_INF; int bestj = 0;
#pragma unroll
        for (int j = 0; j < 32; j++)
            if (v[j] > bestv) { bestv = v[j]; bestj = j; }

#pragma unroll 1
        for (int i = 0; i < KTOP; i++) {
            float wk = bestv;
#pragma unroll
            for (int s = 16; s; s >>= 1)
                wk = fmaxf(wk, __shfl_xor_sync(FULLMASK, wk, s));
            int winner = __ffs(__ballot_sync(FULLMASK, bestv == wk)) - 1;
            if (lane == i) k0 = wk;
            if (lane == winner) {
                mask |= (1u << bestj);           // exact membership, handles ties
                float nb = NEG_INF; int nj = 0;
#pragma unroll
                for (int j = 0; j < 32; j++) {
                    float vj = (j == bestj) ? NEG_INF : v[j];
                    if (j == bestj) v[j] = NEG_INF;
                    if (vj > nb) { nb = vj; nj = j; }
                }
                bestv = nb; bestj = nj;
            }
            __syncwarp();
        }
    }

    mask_out = mask;
    return (lane < KTOP) ? k0 : 0.0f;
}

__global__ void __launch_bounds__(WPB * 32)
topk_main_kernel(const float* __restrict__ A, const float* __restrict__ B,
                 int nrows, float* __restrict__ out) {
    __shared__ float  s_keys[WPB][64];
    __shared__ int    s_match[WPB];
    __shared__ double s_diff[WPB];
    __shared__ int    s_last;

    int w = threadIdx.x >> 5;
    int lane = threadIdx.x & 31;

    int    match_acc = 0;
    double diff_acc  = 0.0;

    for (int row = blockIdx.x * WPB + w; row < nrows; row += NBLK * WPB) {
        unsigned ma, mb;
        float va = process_row(A, row, lane, s_keys[w], ma);
        float vb = process_row(B, row, lane, s_keys[w], mb);

        // diff: sum_k |v_pred[k] - v_topk[k]|  (paired sorted values)
        float d = (lane < KTOP) ? fabsf(va - vb) : 0.0f;
#pragma unroll
        for (int s = 16; s; s >>= 1)
            d += __shfl_xor_sync(FULLMASK, d, s);

        // match: membership-mask intersection; single REDUX for the warp sum
        int m = __reduce_add_sync(FULLMASK, __popc(ma & mb));

        match_acc += m;
        diff_acc  += (double)d;
    }

    if (lane == 0) { s_match[w] = match_acc; s_diff[w] = diff_acc; }
    __syncthreads();

    if (threadIdx.x == 0) {
        int mt = 0; double dt = 0.0;
#pragma unroll
        for (int i = 0; i < WPB; i++) { mt += s_match[i]; dt += s_diff[i]; }
        g_match_part[blockIdx.x] = (float)mt;
        g_diff_part[blockIdx.x]  = dt;
        __threadfence();
        int ticket = atomicAdd(&g_done, 1);
        s_last = (ticket == NBLK - 1) ? 1 : 0;
    }
    __syncthreads();

    // Last finishing block reduces the (L2-hot) partials and writes the output.
    if (s_last) {
        __shared__ double sm[256];
        __shared__ double sd[256];
        double m = 0.0, d = 0.0;
        for (int i = threadIdx.x; i < NBLK; i += WPB * 32) {
            m += (double)g_match_part[i];
            d += g_diff_part[i];
        }
        sm[threadIdx.x] = m;
        sd[threadIdx.x] = d;
        __syncthreads();
        for (int s = (WPB * 32) / 2; s; s >>= 1) {
            if (threadIdx.x < s) {
                sm[threadIdx.x] += sm[threadIdx.x + s];
                sd[threadIdx.x] += sd[threadIdx.x + s];
            }
            __syncthreads();
        }
        if (threadIdx.x == 0) {
            out[0] = (float)(sm[0] / ((double)KTOP * (double)nrows)); // acc
            out[1] = (float)(sd[0] / (double)KTOP);                   // diff
            g_done = 0;   // restore for next graph replay (deterministic)
        }
    }
}

extern "C" void kernel_launch(void* const* d_in, const int* in_sizes, int n_in,
                              void* d_out, int out_size) {
    const float* A = (const float*)d_in[0];  // pred  (metric is symmetric in inputs)
    const float* B = (const float*)d_in[1];  // target
    int nrows = in_sizes[0] / C;

    topk_main_kernel<<<NBLK, WPB * 32>>>(A, B, nrows, (float*)d_out);
}